// round 1
// baseline (speedup 1.0000x reference)
#include <cuda_runtime.h>
#include <cuda_bf16.h>

// Problem dims (fixed by the dataset)
#define MROWS 50176          // 256 * 196
#define DDIM  384
#define HDIM  1536
#define NOUT  (MROWS * DDIM) // 19,267,584 output y elements (+1 optional scalar sf2)

// ---------------------------------------------------------------------------
// Scratch (device globals; no allocations allowed)
// ---------------------------------------------------------------------------
__device__ __align__(256) __nv_bfloat16 g_xq[(size_t)MROWS * DDIM];   // quantized x as bf16 ints
__device__ __align__(256) __nv_bfloat16 g_w1q[(size_t)HDIM * DDIM];   // quantized W1 as bf16 ints
__device__ __align__(256) __nv_bfloat16 g_w2q[(size_t)DDIM * HDIM];   // quantized W2 as bf16 ints
__device__ float g_scale1[HDIM];   // w1_sf * act_sf
__device__ float g_bint1[HDIM];    // round(b1 / scale1)
__device__ float g_w2sf[DDIM];     // w2_sf
__device__ float g_scale2[DDIM];   // w2_sf * sf1   (filled after GEMM1 max)
__device__ float g_bint2[DDIM];    // round(b2 / scale2)
__device__ __align__(256) float g_hbuf[(size_t)MROWS * HDIM];         // fp32 h after relu (308MB)
__device__ unsigned g_max1, g_max2;
__device__ float g_sf1, g_inv_sf1, g_sf2, g_inv_sf2;

// ---------------------------------------------------------------------------
// Small helpers
// ---------------------------------------------------------------------------
__device__ __forceinline__ float clamp8(float v) {
    return fminf(127.0f, fmaxf(-128.0f, v));
}

// ---------------------------------------------------------------------------
// k_init: reset global maxima (graph replays reuse device globals)
// ---------------------------------------------------------------------------
__global__ void k_init() {
    g_max1 = 0u;
    g_max2 = 0u;
}

// ---------------------------------------------------------------------------
// Weight quantization. One block per output channel.
// ---------------------------------------------------------------------------
__global__ void k_quant_w1(const float* __restrict__ W, const float* __restrict__ b,
                           const float* __restrict__ asf) {
    int o = blockIdx.x;                       // 0..HDIM-1
    const float* row = W + (size_t)o * DDIM;
    float m = 0.0f;
    for (int d = threadIdx.x; d < DDIM; d += blockDim.x) m = fmaxf(m, fabsf(row[d]));
    for (int off = 16; off; off >>= 1) m = fmaxf(m, __shfl_xor_sync(0xffffffffu, m, off));
    __shared__ float sred[8];
    __shared__ float s_sf;
    int wid = threadIdx.x >> 5;
    if ((threadIdx.x & 31) == 0) sred[wid] = m;
    __syncthreads();
    if (threadIdx.x == 0) {
        float mm = sred[0];
        for (int i = 1; i < (int)(blockDim.x >> 5); i++) mm = fmaxf(mm, sred[i]);
        float sf = __fdiv_rn(mm, 127.0f);
        s_sf = sf;
        float sc = sf * asf[0];
        g_scale1[o] = sc;
        g_bint1[o]  = rintf(__fdiv_rn(b[o], sc));
    }
    __syncthreads();
    float sf = s_sf;
    for (int d = threadIdx.x; d < DDIM; d += blockDim.x) {
        float v = clamp8(rintf(__fdiv_rn(row[d], sf)));
        g_w1q[(size_t)o * DDIM + d] = __float2bfloat16_rn(v);
    }
}

__global__ void k_quant_w2(const float* __restrict__ W) {
    int o = blockIdx.x;                       // 0..DDIM-1
    const float* row = W + (size_t)o * HDIM;
    float m = 0.0f;
    for (int d = threadIdx.x; d < HDIM; d += blockDim.x) m = fmaxf(m, fabsf(row[d]));
    for (int off = 16; off; off >>= 1) m = fmaxf(m, __shfl_xor_sync(0xffffffffu, m, off));
    __shared__ float sred[8];
    __shared__ float s_sf;
    int wid = threadIdx.x >> 5;
    if ((threadIdx.x & 31) == 0) sred[wid] = m;
    __syncthreads();
    if (threadIdx.x == 0) {
        float mm = sred[0];
        for (int i = 1; i < (int)(blockDim.x >> 5); i++) mm = fmaxf(mm, sred[i]);
        float sf = __fdiv_rn(mm, 127.0f);
        s_sf = sf;
        g_w2sf[o] = sf;
    }
    __syncthreads();
    float sf = s_sf;
    for (int d = threadIdx.x; d < HDIM; d += blockDim.x) {
        float v = clamp8(rintf(__fdiv_rn(row[d], sf)));
        g_w2q[(size_t)o * HDIM + d] = __float2bfloat16_rn(v);
    }
}

// ---------------------------------------------------------------------------
// Quantize x -> bf16 integers (x is already on the act_sf grid)
// ---------------------------------------------------------------------------
__global__ void k_quant_x(const float4* __restrict__ x4, const float* __restrict__ asf) {
    int i = blockIdx.x * blockDim.x + threadIdx.x;
    float inv = __frcp_rn(asf[0]);            // x/asf is near-integer; rcp-mul is safe
    float4 v = x4[i];
    float q0 = clamp8(rintf(v.x * inv));
    float q1 = clamp8(rintf(v.y * inv));
    float q2 = clamp8(rintf(v.z * inv));
    float q3 = clamp8(rintf(v.w * inv));
    __nv_bfloat162 p[2];
    p[0] = __floats2bfloat162_rn(q0, q1);
    p[1] = __floats2bfloat162_rn(q2, q3);
    *reinterpret_cast<uint2*>(g_xq + (size_t)i * 4) = *reinterpret_cast<uint2*>(p);
}

// ---------------------------------------------------------------------------
// After GEMM1 max: sf1, layer-2 scales/bias
// ---------------------------------------------------------------------------
__global__ void k_scale2(const float* __restrict__ b2) {
    int o = threadIdx.x;                      // 0..DDIM-1
    float sf1 = __fdiv_rn(__uint_as_float(g_max1), 127.0f);
    if (o == 0) {
        g_sf1 = sf1;
        g_inv_sf1 = __fdiv_rn(1.0f, sf1);
    }
    float sc = g_w2sf[o] * sf1;
    g_scale2[o] = sc;
    g_bint2[o]  = rintf(__fdiv_rn(b2[o], sc));
}

// ---------------------------------------------------------------------------
// GEMM tile machinery: mma.sync m16n8k16 bf16, BM=BN=128, BK=32, 256 threads
// ---------------------------------------------------------------------------
#define BM 128
#define BN 128
#define BK 32
#define BKP 40   // padded smem row (bf16 elems): conflict-free ldmatrix-style LDS.32

__device__ __forceinline__ void mma16816(float c[4],
                                         unsigned a0, unsigned a1, unsigned a2, unsigned a3,
                                         unsigned b0, unsigned b1) {
    asm volatile(
        "mma.sync.aligned.m16n8k16.row.col.f32.bf16.bf16.f32 "
        "{%0,%1,%2,%3}, {%4,%5,%6,%7}, {%8,%9}, {%0,%1,%2,%3};\n"
        : "+f"(c[0]), "+f"(c[1]), "+f"(c[2]), "+f"(c[3])
        : "r"(a0), "r"(a1), "r"(a2), "r"(a3), "r"(b0), "r"(b1));
}

// Compute one BK=32 slab: warp tile is 64(m) x 32(n): 4 m-tiles x 4 n-tiles
__device__ __forceinline__ void compute_tile(const __nv_bfloat16* sA, const __nv_bfloat16* sB,
                                             float (*acc)[4][4],
                                             int warp_m, int warp_n, int g, int tg) {
#pragma unroll
    for (int ks = 0; ks < 2; ks++) {
        int kk = ks * 16 + 2 * tg;
        unsigned bfr[4][2];
#pragma unroll
        for (int nt = 0; nt < 4; nt++) {
            const __nv_bfloat16* pb = sB + (warp_n * 32 + nt * 8 + g) * BKP + kk;
            bfr[nt][0] = *reinterpret_cast<const unsigned*>(pb);
            bfr[nt][1] = *reinterpret_cast<const unsigned*>(pb + 8);
        }
#pragma unroll
        for (int mt = 0; mt < 4; mt++) {
            const __nv_bfloat16* pa = sA + (warp_m * 64 + mt * 16 + g) * BKP + kk;
            unsigned a0 = *reinterpret_cast<const unsigned*>(pa);
            unsigned a1 = *reinterpret_cast<const unsigned*>(pa + 8 * BKP);
            unsigned a2 = *reinterpret_cast<const unsigned*>(pa + 8);
            unsigned a3 = *reinterpret_cast<const unsigned*>(pa + 8 * BKP + 8);
#pragma unroll
            for (int nt = 0; nt < 4; nt++)
                mma16816(acc[mt][nt], a0, a1, a2, a3, bfr[nt][0], bfr[nt][1]);
        }
    }
}

// ---------------------------------------------------------------------------
// GEMM1: h = relu((xq @ W1q^T + bint1) * scale1); track max(h)
// A: g_xq [M, 384] bf16; B: g_w1q [1536, 384] bf16; out: g_hbuf fp32
// ---------------------------------------------------------------------------
__global__ void __launch_bounds__(256) k_gemm1() {
    __shared__ __nv_bfloat16 sA[2][BM * BKP];
    __shared__ __nv_bfloat16 sB[2][BM * BKP];
    __shared__ float sred[8];

    int tid = threadIdx.x;
    int bx = blockIdx.x;   // N tile (0..11)
    int by = blockIdx.y;   // M tile (0..391)

    const __nv_bfloat16* Ag = g_xq  + (size_t)by * BM * DDIM;
    const __nv_bfloat16* Bg = g_w1q + (size_t)bx * BN * DDIM;

    int lrow = tid >> 2;           // 0..63
    int lcol = (tid & 3) * 8;      // 0,8,16,24

    uint4 la[2], lb[2];
#pragma unroll
    for (int i = 0; i < 2; i++) {
        la[i] = *reinterpret_cast<const uint4*>(Ag + (size_t)(lrow + i * 64) * DDIM + lcol);
        lb[i] = *reinterpret_cast<const uint4*>(Bg + (size_t)(lrow + i * 64) * DDIM + lcol);
    }
#pragma unroll
    for (int i = 0; i < 2; i++) {
        *reinterpret_cast<uint4*>(&sA[0][(lrow + i * 64) * BKP + lcol]) = la[i];
        *reinterpret_cast<uint4*>(&sB[0][(lrow + i * 64) * BKP + lcol]) = lb[i];
    }
    __syncthreads();

    float acc[4][4][4];
#pragma unroll
    for (int a = 0; a < 4; a++)
#pragma unroll
        for (int b = 0; b < 4; b++)
#pragma unroll
            for (int c = 0; c < 4; c++) acc[a][b][c] = 0.0f;

    int lane = tid & 31, wid = tid >> 5;
    int warp_m = wid >> 2, warp_n = wid & 3;
    int g = lane >> 2, tg = lane & 3;

    const int KT = DDIM / BK;  // 12
    for (int kt = 0; kt < KT; kt++) {
        int buf = kt & 1;
        if (kt + 1 < KT) {
            int k0 = (kt + 1) * BK;
#pragma unroll
            for (int i = 0; i < 2; i++) {
                la[i] = *reinterpret_cast<const uint4*>(Ag + (size_t)(lrow + i * 64) * DDIM + k0 + lcol);
                lb[i] = *reinterpret_cast<const uint4*>(Bg + (size_t)(lrow + i * 64) * DDIM + k0 + lcol);
            }
        }
        compute_tile(sA[buf], sB[buf], acc, warp_m, warp_n, g, tg);
        if (kt + 1 < KT) {
            int nb = buf ^ 1;
#pragma unroll
            for (int i = 0; i < 2; i++) {
                *reinterpret_cast<uint4*>(&sA[nb][(lrow + i * 64) * BKP + lcol]) = la[i];
                *reinterpret_cast<uint4*>(&sB[nb][(lrow + i * 64) * BKP + lcol]) = lb[i];
            }
            __syncthreads();
        }
    }

    // Epilogue: dequant + bias + relu, store h fp32, block max
    float lmax = 0.0f;
    int rowbase = by * BM + warp_m * 64;
    int colbase = bx * BN + warp_n * 32;
#pragma unroll
    for (int nt = 0; nt < 4; nt++) {
        int c = colbase + nt * 8 + 2 * tg;
        float s0 = g_scale1[c],     s1 = g_scale1[c + 1];
        float bi0 = g_bint1[c],     bi1 = g_bint1[c + 1];
#pragma unroll
        for (int mt = 0; mt < 4; mt++) {
            int r = rowbase + mt * 16 + g;
            float v0 = fmaxf((acc[mt][nt][0] + bi0) * s0, 0.0f);
            float v1 = fmaxf((acc[mt][nt][1] + bi1) * s1, 0.0f);
            float v2 = fmaxf((acc[mt][nt][2] + bi0) * s0, 0.0f);
            float v3 = fmaxf((acc[mt][nt][3] + bi1) * s1, 0.0f);
            *reinterpret_cast<float2*>(&g_hbuf[(size_t)r * HDIM + c])       = make_float2(v0, v1);
            *reinterpret_cast<float2*>(&g_hbuf[(size_t)(r + 8) * HDIM + c]) = make_float2(v2, v3);
            lmax = fmaxf(lmax, fmaxf(fmaxf(v0, v1), fmaxf(v2, v3)));
        }
    }
    for (int off = 16; off; off >>= 1) lmax = fmaxf(lmax, __shfl_xor_sync(0xffffffffu, lmax, off));
    if (lane == 0) sred[wid] = lmax;
    __syncthreads();
    if (tid == 0) {
        float m = sred[0];
        for (int i = 1; i < 8; i++) m = fmaxf(m, sred[i]);
        atomicMax(&g_max1, __float_as_uint(m));   // nonneg floats: uint order == float order
    }
}

// ---------------------------------------------------------------------------
// GEMM2: y = (quant(h, sf1) @ W2q^T + bint2) * scale2; track max|y|
// A: g_hbuf [M, 1536] fp32 (quantized to bf16 ints in the loader)
// B: g_w2q [384, 1536] bf16; out: y (d_out) fp32 (pre-requant)
// ---------------------------------------------------------------------------
__global__ void __launch_bounds__(256) k_gemm2(float* __restrict__ Y) {
    __shared__ __nv_bfloat16 sA[2][BM * BKP];
    __shared__ __nv_bfloat16 sB[2][BM * BKP];
    __shared__ float sred[8];

    int tid = threadIdx.x;
    int bx = blockIdx.x;   // N tile (0..2)
    int by = blockIdx.y;   // M tile (0..391)

    const float*         Ag = g_hbuf + (size_t)by * BM * HDIM;
    const __nv_bfloat16* Bg = g_w2q  + (size_t)bx * BN * HDIM;

    float inv1 = g_inv_sf1;

    // A loader: 128x32 fp32 = 1024 float4 chunks, 4/thread
    int arow = tid >> 3;           // 0..31
    int acol = (tid & 7) * 4;      // 0,4,...,28
    // B loader: same pattern as GEMM1
    int brow = tid >> 2;           // 0..63
    int bcol = (tid & 3) * 8;

    float4 laf[4];
    uint4 lb[2];
#pragma unroll
    for (int i = 0; i < 4; i++)
        laf[i] = *reinterpret_cast<const float4*>(Ag + (size_t)(arow + i * 32) * HDIM + acol);
#pragma unroll
    for (int i = 0; i < 2; i++)
        lb[i] = *reinterpret_cast<const uint4*>(Bg + (size_t)(brow + i * 64) * HDIM + bcol);

#pragma unroll
    for (int i = 0; i < 4; i++) {
        __nv_bfloat162 p[2];
        p[0] = __floats2bfloat162_rn(clamp8(rintf(laf[i].x * inv1)), clamp8(rintf(laf[i].y * inv1)));
        p[1] = __floats2bfloat162_rn(clamp8(rintf(laf[i].z * inv1)), clamp8(rintf(laf[i].w * inv1)));
        *reinterpret_cast<uint2*>(&sA[0][(arow + i * 32) * BKP + acol]) = *reinterpret_cast<uint2*>(p);
    }
#pragma unroll
    for (int i = 0; i < 2; i++)
        *reinterpret_cast<uint4*>(&sB[0][(brow + i * 64) * BKP + bcol]) = lb[i];
    __syncthreads();

    float acc[4][4][4];
#pragma unroll
    for (int a = 0; a < 4; a++)
#pragma unroll
        for (int b = 0; b < 4; b++)
#pragma unroll
            for (int c = 0; c < 4; c++) acc[a][b][c] = 0.0f;

    int lane = tid & 31, wid = tid >> 5;
    int warp_m = wid >> 2, warp_n = wid & 3;
    int g = lane >> 2, tg = lane & 3;

    const int KT = HDIM / BK;  // 48
    for (int kt = 0; kt < KT; kt++) {
        int buf = kt & 1;
        if (kt + 1 < KT) {
            int k0 = (kt + 1) * BK;
#pragma unroll
            for (int i = 0; i < 4; i++)
                laf[i] = *reinterpret_cast<const float4*>(Ag + (size_t)(arow + i * 32) * HDIM + k0 + acol);
#pragma unroll
            for (int i = 0; i < 2; i++)
                lb[i] = *reinterpret_cast<const uint4*>(Bg + (size_t)(brow + i * 64) * HDIM + k0 + bcol);
        }
        compute_tile(sA[buf], sB[buf], acc, warp_m, warp_n, g, tg);
        if (kt + 1 < KT) {
            int nb = buf ^ 1;
#pragma unroll
            for (int i = 0; i < 4; i++) {
                __nv_bfloat162 p[2];
                p[0] = __floats2bfloat162_rn(clamp8(rintf(laf[i].x * inv1)), clamp8(rintf(laf[i].y * inv1)));
                p[1] = __floats2bfloat162_rn(clamp8(rintf(laf[i].z * inv1)), clamp8(rintf(laf[i].w * inv1)));
                *reinterpret_cast<uint2*>(&sA[nb][(arow + i * 32) * BKP + acol]) = *reinterpret_cast<uint2*>(p);
            }
#pragma unroll
            for (int i = 0; i < 2; i++)
                *reinterpret_cast<uint4*>(&sB[nb][(brow + i * 64) * BKP + bcol]) = lb[i];
            __syncthreads();
        }
    }

    // Epilogue: dequant + bias, store y fp32, block max of |y|
    float lmax = 0.0f;
    int rowbase = by * BM + warp_m * 64;
    int colbase = bx * BN + warp_n * 32;
#pragma unroll
    for (int nt = 0; nt < 4; nt++) {
        int c = colbase + nt * 8 + 2 * tg;
        float s0 = g_scale2[c],   s1 = g_scale2[c + 1];
        float bi0 = g_bint2[c],   bi1 = g_bint2[c + 1];
#pragma unroll
        for (int mt = 0; mt < 4; mt++) {
            int r = rowbase + mt * 16 + g;
            float v0 = (acc[mt][nt][0] + bi0) * s0;
            float v1 = (acc[mt][nt][1] + bi1) * s1;
            float v2 = (acc[mt][nt][2] + bi0) * s0;
            float v3 = (acc[mt][nt][3] + bi1) * s1;
            *reinterpret_cast<float2*>(&Y[(size_t)r * DDIM + c])       = make_float2(v0, v1);
            *reinterpret_cast<float2*>(&Y[(size_t)(r + 8) * DDIM + c]) = make_float2(v2, v3);
            lmax = fmaxf(lmax, fmaxf(fmaxf(fabsf(v0), fabsf(v1)), fmaxf(fabsf(v2), fabsf(v3))));
        }
    }
    for (int off = 16; off; off >>= 1) lmax = fmaxf(lmax, __shfl_xor_sync(0xffffffffu, lmax, off));
    if (lane == 0) sred[wid] = lmax;
    __syncthreads();
    if (tid == 0) {
        float m = sred[0];
        for (int i = 1; i < 8; i++) m = fmaxf(m, sred[i]);
        atomicMax(&g_max2, __float_as_uint(m));
    }
}

// ---------------------------------------------------------------------------
// Final scalar stage + in-place output requant
// ---------------------------------------------------------------------------
__global__ void k_sf2(float* __restrict__ out, int writeExtra) {
    float sf2 = __fdiv_rn(__uint_as_float(g_max2), 127.0f);
    g_sf2 = sf2;
    g_inv_sf2 = __fdiv_rn(1.0f, sf2);
    if (writeExtra) out[NOUT] = sf2;
}

__global__ void k_requant(float4* __restrict__ y) {
    int i = blockIdx.x * blockDim.x + threadIdx.x;
    float s = g_sf2, inv = g_inv_sf2;
    float4 v = y[i];
    v.x = clamp8(rintf(v.x * inv)) * s;
    v.y = clamp8(rintf(v.y * inv)) * s;
    v.z = clamp8(rintf(v.z * inv)) * s;
    v.w = clamp8(rintf(v.w * inv)) * s;
    y[i] = v;
}

// ---------------------------------------------------------------------------
// Launch
// ---------------------------------------------------------------------------
extern "C" void kernel_launch(void* const* d_in, const int* in_sizes, int n_in,
                              void* d_out, int out_size) {
    (void)in_sizes; (void)n_in;
    const float* x   = (const float*)d_in[0];
    const float* W1  = (const float*)d_in[1];
    const float* b1  = (const float*)d_in[2];
    const float* W2  = (const float*)d_in[3];
    const float* b2  = (const float*)d_in[4];
    const float* asf = (const float*)d_in[5];
    float* y = (float*)d_out;

    k_init<<<1, 1>>>();
    k_quant_w1<<<HDIM, 128>>>(W1, b1, asf);
    k_quant_w2<<<DDIM, 256>>>(W2);
    k_quant_x<<<(NOUT / 4) / 256, 256>>>((const float4*)x, asf);
    k_gemm1<<<dim3(HDIM / BN, MROWS / BM), 256>>>();
    k_scale2<<<1, DDIM>>>(b2);
    k_gemm2<<<dim3(DDIM / BN, MROWS / BM), 256>>>(y);
    k_sf2<<<1, 1>>>(y, (out_size > NOUT) ? 1 : 0);
    k_requant<<<(NOUT / 4) / 256, 256>>>((float4*)y);
}

// round 4
// speedup vs baseline: 1.6106x; 1.6106x over previous
#include <cuda_runtime.h>
#include <cuda_bf16.h>
#include <cstdint>

#define MROWS 50176          // 256 * 196
#define DDIM  384
#define HDIM  1536
#define NOUT  (MROWS * DDIM)

// ---------------------------------------------------------------------------
// Scratch (device globals). Total ~98 MB — well under the known-passing level.
// ---------------------------------------------------------------------------
__device__ __align__(256) signed char g_xq[(size_t)MROWS * DDIM];   // x as s8
__device__ __align__(256) signed char g_hq[(size_t)MROWS * HDIM];   // quantized h as s8
__device__ __align__(256) signed char g_w1q[(size_t)HDIM * DDIM];
__device__ __align__(256) signed char g_w2q[(size_t)DDIM * HDIM];
__device__ float g_scale1[HDIM];
__device__ int   g_bint1[HDIM];
__device__ float g_w2sf[DDIM];
__device__ float g_scale2[DDIM];
__device__ int   g_bint2[DDIM];
__device__ unsigned g_max1, g_max2;
__device__ float g_sf1, g_inv_sf1, g_sf2, g_inv_sf2;

__device__ __forceinline__ float clamp8(float v) {
    return fminf(127.0f, fmaxf(-128.0f, v));
}

// ---------------------------------------------------------------------------
// PTX helpers (sm_100 baseline ISA: cp.async, ldmatrix, mma.sync IMMA)
// ---------------------------------------------------------------------------
__device__ __forceinline__ void cp16(uint32_t dst, const void* src) {
    asm volatile("cp.async.cg.shared.global [%0], [%1], 16;" :: "r"(dst), "l"(src) : "memory");
}
__device__ __forceinline__ void cp_commit() {
    asm volatile("cp.async.commit_group;" ::: "memory");
}
__device__ __forceinline__ void ldsm4(uint32_t* r, uint32_t addr) {
    asm volatile("ldmatrix.sync.aligned.m8n8.x4.shared.b16 {%0,%1,%2,%3}, [%4];"
                 : "=r"(r[0]), "=r"(r[1]), "=r"(r[2]), "=r"(r[3]) : "r"(addr));
}
__device__ __forceinline__ void imma16832(int c[4],
                                          uint32_t a0, uint32_t a1, uint32_t a2, uint32_t a3,
                                          uint32_t b0, uint32_t b1) {
    asm volatile(
        "mma.sync.aligned.m16n8k32.row.col.s32.s8.s8.s32 "
        "{%0,%1,%2,%3}, {%4,%5,%6,%7}, {%8,%9}, {%0,%1,%2,%3};\n"
        : "+r"(c[0]), "+r"(c[1]), "+r"(c[2]), "+r"(c[3])
        : "r"(a0), "r"(a1), "r"(a2), "r"(a3), "r"(b0), "r"(b1));
}

// ---------------------------------------------------------------------------
// Small kernels
// ---------------------------------------------------------------------------
__global__ void k_init() { g_max1 = 0u; g_max2 = 0u; }

__global__ void k_quant_w1(const float* __restrict__ W, const float* __restrict__ b,
                           const float* __restrict__ asf) {
    int o = blockIdx.x;
    const float* row = W + (size_t)o * DDIM;
    float m = 0.0f;
    for (int d = threadIdx.x; d < DDIM; d += blockDim.x) m = fmaxf(m, fabsf(row[d]));
    for (int off = 16; off; off >>= 1) m = fmaxf(m, __shfl_xor_sync(0xffffffffu, m, off));
    __shared__ float sred[8]; __shared__ float s_sf;
    int wid = threadIdx.x >> 5;
    if ((threadIdx.x & 31) == 0) sred[wid] = m;
    __syncthreads();
    if (threadIdx.x == 0) {
        float mm = sred[0];
        for (int i = 1; i < (int)(blockDim.x >> 5); i++) mm = fmaxf(mm, sred[i]);
        float sf = __fdiv_rn(mm, 127.0f);
        s_sf = sf;
        float sc = sf * asf[0];
        g_scale1[o] = sc;
        g_bint1[o]  = __float2int_rn(__fdiv_rn(b[o], sc));
    }
    __syncthreads();
    float sf = s_sf;
    for (int d = threadIdx.x; d < DDIM; d += blockDim.x) {
        g_w1q[(size_t)o * DDIM + d] = (signed char)(int)clamp8(rintf(__fdiv_rn(row[d], sf)));
    }
}

__global__ void k_quant_w2(const float* __restrict__ W) {
    int o = blockIdx.x;
    const float* row = W + (size_t)o * HDIM;
    float m = 0.0f;
    for (int d = threadIdx.x; d < HDIM; d += blockDim.x) m = fmaxf(m, fabsf(row[d]));
    for (int off = 16; off; off >>= 1) m = fmaxf(m, __shfl_xor_sync(0xffffffffu, m, off));
    __shared__ float sred[8]; __shared__ float s_sf;
    int wid = threadIdx.x >> 5;
    if ((threadIdx.x & 31) == 0) sred[wid] = m;
    __syncthreads();
    if (threadIdx.x == 0) {
        float mm = sred[0];
        for (int i = 1; i < (int)(blockDim.x >> 5); i++) mm = fmaxf(mm, sred[i]);
        float sf = __fdiv_rn(mm, 127.0f);
        s_sf = sf;
        g_w2sf[o] = sf;
    }
    __syncthreads();
    float sf = s_sf;
    for (int d = threadIdx.x; d < HDIM; d += blockDim.x) {
        g_w2q[(size_t)o * HDIM + d] = (signed char)(int)clamp8(rintf(__fdiv_rn(row[d], sf)));
    }
}

__global__ void k_quant_x(const float4* __restrict__ x4, const float* __restrict__ asf) {
    int i = blockIdx.x * blockDim.x + threadIdx.x;
    float inv = __frcp_rn(asf[0]);
    float4 v = x4[i];
    int q0 = (int)clamp8(rintf(v.x * inv));
    int q1 = (int)clamp8(rintf(v.y * inv));
    int q2 = (int)clamp8(rintf(v.z * inv));
    int q3 = (int)clamp8(rintf(v.w * inv));
    uint32_t p = (uint32_t)(q0 & 0xFF) | ((uint32_t)(q1 & 0xFF) << 8)
               | ((uint32_t)(q2 & 0xFF) << 16) | ((uint32_t)(q3 & 0xFF) << 24);
    reinterpret_cast<uint32_t*>(g_xq)[i] = p;
}

__global__ void k_scale2(const float* __restrict__ b2) {
    int o = threadIdx.x;
    float sf1 = __fdiv_rn(__uint_as_float(g_max1), 127.0f);
    if (o == 0) { g_sf1 = sf1; g_inv_sf1 = __fdiv_rn(1.0f, sf1); }
    float sc = g_w2sf[o] * sf1;
    g_scale2[o] = sc;
    g_bint2[o]  = __float2int_rn(__fdiv_rn(b2[o], sc));
}

__global__ void k_sf2(float* __restrict__ out, int writeExtra) {
    float sf2 = __fdiv_rn(__uint_as_float(g_max2), 127.0f);
    g_sf2 = sf2;
    g_inv_sf2 = __fdiv_rn(1.0f, sf2);
    if (writeExtra) out[NOUT] = sf2;
}

__global__ void k_requant(float4* __restrict__ y) {
    int i = blockIdx.x * blockDim.x + threadIdx.x;
    float s = g_sf2, inv = g_inv_sf2;
    float4 v = y[i];
    v.x = clamp8(rintf(v.x * inv)) * s;
    v.y = clamp8(rintf(v.y * inv)) * s;
    v.z = clamp8(rintf(v.z * inv)) * s;
    v.w = clamp8(rintf(v.w * inv)) * s;
    y[i] = v;
}

// ---------------------------------------------------------------------------
// GEMM: s8 IMMA, CTA 128x128, K-slab = 128 bytes (= 128 s8), 3-stage cp.async,
// ldmatrix feeds. Swizzle: 16B-chunk' = chunk ^ (row & 7); rows are 128 B.
// EPI=0: gemm1 pass A -> max(relu(h)) only, no stores
// EPI=1: gemm1 pass B -> write quantized h (s8) to g_hq
// EPI=2: gemm2       -> write y fp32 + max|y|
// KBYTES: row stride in bytes (= K elements): 384 for gemm1, 1536 for gemm2.
// ---------------------------------------------------------------------------
#define STAGES 3
#define STAGE_BYTES 16384              // 128 rows x 128 B
#define GEMM_SMEM (STAGES * 2 * STAGE_BYTES + 1024)

template<int KBYTES, int EPI>
__global__ void __launch_bounds__(256, 2) k_gemm(float* __restrict__ Y) {
    extern __shared__ char smem[];
    __shared__ float s_scale[128];
    __shared__ int   s_bint[128];
    __shared__ float s_red[8];

    const uint32_t sbase = (uint32_t)__cvta_generic_to_shared(smem);
    const uint32_t dataBase = (sbase + 1023u) & ~1023u;
    const int tid = threadIdx.x;
    const int wid = tid >> 5, lane = tid & 31;
    const int bx = blockIdx.x, by = blockIdx.y;
    const int warp_m = wid >> 2, warp_n = wid & 3;

    const signed char* Aptr = (EPI == 2) ? g_hq  : g_xq;
    const signed char* Bptr = (EPI == 2) ? g_w2q : g_w1q;
    const float* SC = (EPI == 2) ? g_scale2 : g_scale1;
    const int*   BI = (EPI == 2) ? g_bint2  : g_bint1;

    if (tid < 128) s_scale[tid] = SC[bx * 128 + tid];
    else           s_bint[tid - 128] = BI[bx * 128 + tid - 128];

    const char* Abase = (const char*)Aptr + (size_t)by * 128 * KBYTES;
    const char* Bbase = (const char*)Bptr + (size_t)bx * 128 * KBYTES;

    auto load_tile = [&](int kt, int s) {
        uint32_t da = dataBase + s * STAGE_BYTES;
        uint32_t db = dataBase + STAGES * STAGE_BYTES + s * STAGE_BYTES;
        size_t koff = (size_t)kt * 128;
#pragma unroll
        for (int it = 0; it < 4; it++) {
            int idx = tid + it * 256;
            int row = idx >> 3, j = idx & 7;
            uint32_t so = (uint32_t)(row * 128) + (uint32_t)((j ^ (row & 7)) << 4);
            cp16(da + so, Abase + (size_t)row * KBYTES + koff + j * 16);
            cp16(db + so, Bbase + (size_t)row * KBYTES + koff + j * 16);
        }
        cp_commit();
    };

    int acc[4][4][4];
#pragma unroll
    for (int a = 0; a < 4; a++)
#pragma unroll
        for (int b = 0; b < 4; b++)
#pragma unroll
            for (int c = 0; c < 4; c++) acc[a][b][c] = 0;

    constexpr int KT = KBYTES / 128;
    load_tile(0, 0);
    if (KT > 1) load_tile(1, 1);

    for (int kt = 0; kt < KT; kt++) {
        if (kt == KT - 1) asm volatile("cp.async.wait_group 0;" ::: "memory");
        else              asm volatile("cp.async.wait_group 1;" ::: "memory");
        __syncthreads();
        if (kt + 2 < KT) load_tile(kt + 2, (kt + 2) % STAGES);

        uint32_t sa = dataBase + (kt % STAGES) * STAGE_BYTES;
        uint32_t sb = dataBase + STAGES * STAGE_BYTES + (kt % STAGES) * STAGE_BYTES;
#pragma unroll
        for (int ks = 0; ks < 4; ks++) {         // 4 x k32 per 128-B slab
            int c0 = 2 * ks;                     // 16B-chunk base
            uint32_t afr[4][4];
#pragma unroll
            for (int mt = 0; mt < 4; mt++) {
                int row = warp_m * 64 + mt * 16 + (lane & 15);
                int ch = c0 + (lane >> 4);
                ldsm4(afr[mt], sa + (uint32_t)(row * 128) + (uint32_t)((ch ^ (row & 7)) << 4));
            }
            uint32_t bfr[2][4];
#pragma unroll
            for (int nb = 0; nb < 2; nb++) {
                int row = warp_n * 32 + nb * 16 + (lane & 7) + ((lane >> 4) << 3);
                int ch = c0 + ((lane >> 3) & 1);
                ldsm4(bfr[nb], sb + (uint32_t)(row * 128) + (uint32_t)((ch ^ (row & 7)) << 4));
            }
#pragma unroll
            for (int mt = 0; mt < 4; mt++)
#pragma unroll
                for (int nt = 0; nt < 4; nt++)
                    imma16832(acc[mt][nt],
                              afr[mt][0], afr[mt][1], afr[mt][2], afr[mt][3],
                              bfr[nt >> 1][(nt & 1) * 2], bfr[nt >> 1][(nt & 1) * 2 + 1]);
        }
    }

    // ------------------------- epilogue -------------------------
    int g  = lane >> 2, tg = lane & 3;
    float lmax = 0.0f;
    const int rowbase = by * 128 + warp_m * 64;
    float inv1 = (EPI == 1) ? g_inv_sf1 : 0.0f;
#pragma unroll
    for (int nt = 0; nt < 4; nt++) {
        int cl = warp_n * 32 + nt * 8 + 2 * tg;
        int cglob = bx * 128 + cl;
        float s0 = s_scale[cl],  s1 = s_scale[cl + 1];
        int  bi0 = s_bint[cl],   bi1 = s_bint[cl + 1];
#pragma unroll
        for (int mt = 0; mt < 4; mt++) {
            int r = rowbase + mt * 16 + g;
            float v0 = __int2float_rn(acc[mt][nt][0] + bi0) * s0;
            float v1 = __int2float_rn(acc[mt][nt][1] + bi1) * s1;
            float v2 = __int2float_rn(acc[mt][nt][2] + bi0) * s0;
            float v3 = __int2float_rn(acc[mt][nt][3] + bi1) * s1;
            if (EPI == 0) {
                v0 = fmaxf(v0, 0.0f); v1 = fmaxf(v1, 0.0f);
                v2 = fmaxf(v2, 0.0f); v3 = fmaxf(v3, 0.0f);
                lmax = fmaxf(lmax, fmaxf(fmaxf(v0, v1), fmaxf(v2, v3)));
            } else if (EPI == 1) {
                v0 = fmaxf(v0, 0.0f); v1 = fmaxf(v1, 0.0f);
                v2 = fmaxf(v2, 0.0f); v3 = fmaxf(v3, 0.0f);
                int q0 = (int)clamp8(rintf(v0 * inv1));
                int q1 = (int)clamp8(rintf(v1 * inv1));
                int q2 = (int)clamp8(rintf(v2 * inv1));
                int q3 = (int)clamp8(rintf(v3 * inv1));
                *reinterpret_cast<short*>(g_hq + (size_t)r * HDIM + cglob) =
                    (short)((q0 & 0xFF) | ((q1 & 0xFF) << 8));
                *reinterpret_cast<short*>(g_hq + (size_t)(r + 8) * HDIM + cglob) =
                    (short)((q2 & 0xFF) | ((q3 & 0xFF) << 8));
            } else {
                lmax = fmaxf(lmax, fmaxf(fmaxf(fabsf(v0), fabsf(v1)),
                                          fmaxf(fabsf(v2), fabsf(v3))));
                *reinterpret_cast<float2*>(&Y[(size_t)r * DDIM + cglob])       = make_float2(v0, v1);
                *reinterpret_cast<float2*>(&Y[(size_t)(r + 8) * DDIM + cglob]) = make_float2(v2, v3);
            }
        }
    }
    if (EPI != 1) {
        for (int off = 16; off; off >>= 1) lmax = fmaxf(lmax, __shfl_xor_sync(0xffffffffu, lmax, off));
        if (lane == 0) s_red[wid] = lmax;
        __syncthreads();
        if (tid == 0) {
            float m = s_red[0];
#pragma unroll
            for (int i = 1; i < 8; i++) m = fmaxf(m, s_red[i]);
            atomicMax(EPI == 0 ? &g_max1 : &g_max2, __float_as_uint(m));
        }
    }
}

// ---------------------------------------------------------------------------
// Launch
// ---------------------------------------------------------------------------
extern "C" void kernel_launch(void* const* d_in, const int* in_sizes, int n_in,
                              void* d_out, int out_size) {
    (void)in_sizes; (void)n_in;
    const float* x   = (const float*)d_in[0];
    const float* W1  = (const float*)d_in[1];
    const float* b1  = (const float*)d_in[2];
    const float* W2  = (const float*)d_in[3];
    const float* b2  = (const float*)d_in[4];
    const float* asf = (const float*)d_in[5];
    float* y = (float*)d_out;

    cudaFuncSetAttribute(k_gemm<DDIM, 0>, cudaFuncAttributeMaxDynamicSharedMemorySize, GEMM_SMEM);
    cudaFuncSetAttribute(k_gemm<DDIM, 1>, cudaFuncAttributeMaxDynamicSharedMemorySize, GEMM_SMEM);
    cudaFuncSetAttribute(k_gemm<HDIM, 2>, cudaFuncAttributeMaxDynamicSharedMemorySize, GEMM_SMEM);

    k_init<<<1, 1>>>();
    k_quant_w1<<<HDIM, 128>>>(W1, b1, asf);
    k_quant_w2<<<DDIM, 256>>>(W2);
    k_quant_x<<<(NOUT / 4) / 256, 256>>>((const float4*)x, asf);

    dim3 g1(HDIM / 128, MROWS / 128);   // 12 x 392
    dim3 g2(DDIM / 128, MROWS / 128);   // 3  x 392
    k_gemm<DDIM, 0><<<g1, 256, GEMM_SMEM>>>(y);   // max(relu(h)) only
    k_scale2<<<1, DDIM>>>(b2);
    k_gemm<DDIM, 1><<<g1, 256, GEMM_SMEM>>>(y);   // write quantized h (s8)
    k_gemm<HDIM, 2><<<g2, 256, GEMM_SMEM>>>(y);   // y fp32 + max|y|
    k_sf2<<<1, 1>>>(y, (out_size > NOUT) ? 1 : 0);
    k_requant<<<(NOUT / 4) / 256, 256>>>((float4*)y);
}